// round 12
// baseline (speedup 1.0000x reference)
#include <cuda_runtime.h>

#define NG      1024
#define IMG_W   256
#define IMG_H   256
#define TILE_SZ 64
#define FOCALF  256.0f
#define LOG2E   1.4426950408889634f

#define BLK_W   16
#define BLK_H   16
#define PAD     1.0f
#define NBLK    ((IMG_W / BLK_W) * (IMG_H / BLK_H))   // 256
#define NTHR    512
#define NPX     (BLK_W * BLK_H)                        // 256
#define NTILE   16

__device__ __forceinline__ float frcp(float x) {
    float r; asm("rcp.approx.ftz.f32 %0, %1;" : "=f"(r) : "f"(x)); return r;
}
__device__ __forceinline__ float flg2(float x) {
    float r; asm("lg2.approx.f32 %0, %1;" : "=f"(r) : "f"(x)); return r;
}
__device__ __forceinline__ float fex2(float x) {
    float r; asm("ex2.approx.ftz.f32 %0, %1;" : "=f"(r) : "f"(x)); return r;
}

// ---------------- device scratch: per-tile depth-sorted lists ----------------
__device__ float4 g_tA[NTILE][NG];    // (mx, my, k2, lg2(op))
__device__ float4 g_tB[NTILE][NG];    // (r, g, b, depth)
__device__ float  g_tRad[NTILE][NG];  // radii (5*sigma)
__device__ int    g_tCnt[NTILE];

// ---------------- 1) per-tile project + cull + depth sort ----------------
__global__ void __launch_bounds__(1024) k_prep(
        const float* __restrict__ means3d,
        const float* __restrict__ opacity,
        const float* __restrict__ scale3d,
        const float* __restrict__ features,
        const float* __restrict__ V,
        const float* __restrict__ P) {

    __shared__ unsigned long long sKey[NG];
    __shared__ float M[16];
    __shared__ int s_cnt;

    const int tid  = threadIdx.x;
    const int lane = tid & 31;
    const int tile = blockIdx.x;

    if (tid < 16) {
        int r = tid & 3, c = tid >> 2;
        float mm;
        if (c < 3) {
            int pc = (c == 2) ? 3 : c;
            mm = V[r*4+0]*P[0*4+pc] + V[r*4+1]*P[1*4+pc]
               + V[r*4+2]*P[2*4+pc] + V[r*4+3]*P[3*4+pc];
        } else {
            mm = V[r*4+2];
        }
        M[c*4 + r] = mm;
    }
    if (tid == 0) s_cnt = 0;

    const float tu0 = (float)((tile & 3) * TILE_SZ);
    const float tv0 = (float)((tile >> 2) * TILE_SZ);
    const float tu1 = tu0 + (float)TILE_SZ - 1.0f;
    const float tv1 = tv0 + (float)TILE_SZ - 1.0f;

    float x  = means3d[3*tid+0];
    float y  = means3d[3*tid+1];
    float z  = means3d[3*tid+2];
    float sc = scale3d[tid];

    __syncthreads();                              // M ready

    float ph0 = fmaf(x, M[0],  fmaf(y, M[1],  fmaf(z, M[2],  M[3])));
    float ph1 = fmaf(x, M[4],  fmaf(y, M[5],  fmaf(z, M[6],  M[7])));
    float ph3 = fmaf(x, M[8],  fmaf(y, M[9],  fmaf(z, M[10], M[11])));
    float tz  = fmaf(x, M[12], fmaf(y, M[13], fmaf(z, M[14], M[15])));

    float invw = frcp(ph3 + 1e-6f);
    float mx = fmaf(ph0 * invw, 128.0f, 127.5f);
    float my = fmaf(ph1 * invw, 128.0f, 127.5f);

    float rtz   = frcp(tz);
    float s2    = sc * FOCALF * rtz;
    float radii = 5.0f * s2;
    float rs2   = frcp(s2);
    float k2    = (-0.5f * LOG2E) * rs2 * rs2;

    // exact reference tile mask (unclamped rect equivalent for strict >)
    bool m = (fminf(mx + radii, tu1) > fmaxf(mx - radii, tu0)) &&
             (fminf(my + radii, tv1) > fmaxf(my - radii, tv0));

    unsigned bal = __ballot_sync(0xffffffffu, m);
    unsigned long long myKey = 0;
    float lop = 0.0f, fr = 0.0f, fg = 0.0f, fb = 0.0f;
    if (m) {
        int prefix = __popc(bal & ((1u << lane) - 1u));
        int leader = __ffs(bal) - 1;
        int wbase = 0;
        if (lane == leader) wbase = atomicAdd(&s_cnt, __popc(bal));
        wbase = __shfl_sync(bal, wbase, leader);
        unsigned ku = __float_as_uint(tz);
        ku = (ku & 0x80000000u) ? ~ku : (ku | 0x80000000u);
        myKey = ((unsigned long long)ku << 32) | (unsigned)tid;  // unique, stable
        sKey[wbase + prefix] = myKey;
        lop = flg2(opacity[tid]);                 // winner-only loads
        fr = features[3*tid+0];
        fg = features[3*tid+1];
        fb = features[3*tid+2];
    }
    __syncthreads();
    const int cnt = s_cnt;

    // cooperative warp rank
    int myR = -1;
    for (unsigned b = bal; b; b &= b - 1) {
        int wl = __ffs(b) - 1;
        unsigned long long k = __shfl_sync(0xffffffffu, myKey, wl);
        int c = 0;
        for (int j = lane; j < cnt; j += 32) c += (sKey[j] < k) ? 1 : 0;
        c = __reduce_add_sync(0xffffffffu, c);
        if (lane == wl) myR = c;
    }
    if (m) {
        g_tA[tile][myR]   = make_float4(mx, my, k2, lop);
        g_tB[tile][myR]   = make_float4(fr, fg, fb, tz);
        g_tRad[tile][myR] = radii;
    }
    if (tid == 0) g_tCnt[tile] = cnt;
}

// ---------------- 2) render: filter tile list + composite ----------------
__global__ void __launch_bounds__(NTHR, 2) k_render(float* __restrict__ out) {
    __shared__ float4 sA[NG];          // 16 KB (worst-case tile count)
    __shared__ float4 sB[NG];          // 16 KB
    __shared__ int chunkCnt[32];
    __shared__ int chunkBase[33];
    __shared__ float xb[5 * NPX];      // 5 KB

    const int tid  = threadIdx.x;
    const int lane = tid & 31;
    const int wid  = tid >> 5;

    const int bx = blockIdx.x & 15;
    const int by = blockIdx.x >> 4;
    const int x0 = bx * BLK_W;
    const int y0 = by * BLK_H;
    const int tile = (by >> 2) * 4 + (bx >> 2);

    const float cx = (float)x0 + (BLK_W - 1) * 0.5f;
    const float cy = (float)y0 + (BLK_H - 1) * 0.5f;
    const float hw = (BLK_W - 1) * 0.5f + PAD;
    const float hh = (BLK_H - 1) * 0.5f + PAD;

    const int cnt = g_tCnt[tile];
    const float4* __restrict__ TA = g_tA[tile];
    const float4* __restrict__ TB = g_tB[tile];
    const float*  __restrict__ TR = g_tRad[tile];

    if (tid < 32) chunkCnt[tid] = 0;
    __syncthreads();

    // pass 1: stable circle-cull; warp w owns 32-entry chunks w and w+16
    float4 kA[2], kB[2];
    unsigned kbal[2];
    bool keep[2] = {false, false};

    #pragma unroll
    for (int p = 0; p < 2; p++) {
        int c = wid + p * 16;
        int j = c * 32 + lane;
        bool k = false;
        float4 A, B;
        if (j < cnt) {
            float rad = TR[j];
            A = TA[j];
            float ddx = fmaxf(fabsf(A.x - cx) - hw, 0.0f);
            float ddy = fmaxf(fabsf(A.y - cy) - hh, 0.0f);
            k = fmaf(ddx, ddx, ddy * ddy) < rad * rad;
            if (k) B = TB[j];
        }
        unsigned bal = __ballot_sync(0xffffffffu, k);
        if (lane == 0) chunkCnt[c] = __popc(bal);
        kA[p] = A; kB[p] = B; kbal[p] = bal; keep[p] = k;
    }
    __syncthreads();

    // exclusive scan of 32 chunk counts (warp 0)
    if (wid == 0) {
        int v = chunkCnt[lane];
        #pragma unroll
        for (int off = 1; off < 32; off <<= 1) {
            int n = __shfl_up_sync(0xffffffffu, v, off);
            if (lane >= off) v += n;
        }
        chunkBase[lane + 1] = v;
        if (lane == 0) chunkBase[0] = 0;
    }
    __syncthreads();
    const int scnt = chunkBase[32];

    // pass 2: stable write (preserves depth order)
    #pragma unroll
    for (int p = 0; p < 2; p++) {
        if (keep[p]) {
            int c = wid + p * 16;
            int pos = chunkBase[c] + __popc(kbal[p] & ((1u << lane) - 1u));
            sA[pos] = kA[p];
            sB[pos] = kB[p];
        }
    }
    __syncthreads();

    // ---- split-list composite: 2 threads per pixel ----
    const int pxi = tid & (NPX - 1);
    const int px  = x0 + (pxi & (BLK_W - 1));
    const int py  = y0 + (pxi / BLK_W);
    const float fx = (float)px, fy = (float)py;
    const bool back = (tid >= NPX);

    const int half = (scnt + 1) >> 1;
    const int j0 = back ? half : 0;
    const int j1 = back ? scnt : half;

    float T = 1.0f;
    unsigned long long crg = 0ull, cbd = 0ull;

    #pragma unroll 4
    for (int j = j0; j < j1; j++) {
        float4 A = sA[j];
        float dx = fx - A.x;
        float dy = fy - A.y;
        float d2 = fmaf(dx, dx, dy * dy);
        float a  = fex2(fmaf(A.z, d2, A.w));      // = op*gw <= 0.95 < 0.99
        float w  = a * T;
        ulonglong2 B = reinterpret_cast<const ulonglong2*>(sB)[j];
        unsigned long long ww;
        unsigned wu = __float_as_uint(w);
        asm("mov.b64 %0, {%1, %1};" : "=l"(ww) : "r"(wu));
        asm("fma.rn.f32x2 %0, %1, %2, %3;" : "=l"(crg) : "l"(B.x), "l"(ww), "l"(crg));
        asm("fma.rn.f32x2 %0, %1, %2, %3;" : "=l"(cbd) : "l"(B.y), "l"(ww), "l"(cbd));
        T = fmaf(-a, T, T);
    }

    float cr, cg, cb, dsum;
    { unsigned lo, hi;
      asm("mov.b64 {%0, %1}, %2;" : "=r"(lo), "=r"(hi) : "l"(crg));
      cr = __uint_as_float(lo); cg = __uint_as_float(hi);
      asm("mov.b64 {%0, %1}, %2;" : "=r"(lo), "=r"(hi) : "l"(cbd));
      cb = __uint_as_float(lo); dsum = __uint_as_float(hi); }

    if (back) {
        xb[0*NPX + pxi] = cr;
        xb[1*NPX + pxi] = cg;
        xb[2*NPX + pxi] = cb;
        xb[3*NPX + pxi] = dsum;
        xb[4*NPX + pxi] = T;
    }
    __syncthreads();

    if (!back) {
        // (C,T) o (C',T') = (C + T*C', T*T')  -- exact composition
        cr   = fmaf(T, xb[0*NPX + pxi], cr);
        cg   = fmaf(T, xb[1*NPX + pxi], cg);
        cb   = fmaf(T, xb[2*NPX + pxi], cb);
        dsum = fmaf(T, xb[3*NPX + pxi], dsum);
        T    = T * xb[4*NPX + pxi];

        float acc = 1.0f - T;
        float bg  = T;
        int pix = py * IMG_W + px;
        out[pix*3 + 0] = fminf(fmaxf(cr + bg, 0.0f), 1.0f);
        out[pix*3 + 1] = fminf(fmaxf(cg + bg, 0.0f), 1.0f);
        out[pix*3 + 2] = fminf(fmaxf(cb + bg, 0.0f), 1.0f);
        out[IMG_W*IMG_H*3 + pix] = dsum;
        out[IMG_W*IMG_H*4 + pix] = acc;
    }
}

extern "C" void kernel_launch(void* const* d_in, const int* in_sizes, int n_in,
                              void* d_out, int out_size) {
    const float* means3d  = (const float*)d_in[0];
    const float* opacity  = (const float*)d_in[1];
    const float* scale3d  = (const float*)d_in[2];
    const float* features = (const float*)d_in[3];
    const float* viewm    = (const float*)d_in[4];
    const float* projm    = (const float*)d_in[5];
    float* out = (float*)d_out;

    k_prep<<<NTILE, 1024>>>(means3d, opacity, scale3d, features, viewm, projm);
    k_render<<<NBLK, NTHR>>>(out);
}

// round 13
// speedup vs baseline: 1.1953x; 1.1953x over previous
#include <cuda_runtime.h>

#define NG      1024
#define IMG_W   256
#define IMG_H   256
#define TILE_SZ 64
#define FOCALF  256.0f
#define LOG2E   1.4426950408889634f

#define BLK_W   16
#define BLK_H   16
#define PAD     1.0f
#define NBLK    ((IMG_W / BLK_W) * (IMG_H / BLK_H))   // 256
#define NTHR    512
#define NPX     (BLK_W * BLK_H)                        // 256

__device__ __forceinline__ float frcp(float x) {
    float r; asm("rcp.approx.ftz.f32 %0, %1;" : "=f"(r) : "f"(x)); return r;
}
__device__ __forceinline__ float flg2(float x) {
    float r; asm("lg2.approx.f32 %0, %1;" : "=f"(r) : "f"(x)); return r;
}
__device__ __forceinline__ float fex2(float x) {
    float r; asm("ex2.approx.ftz.f32 %0, %1;" : "=f"(r) : "f"(x)); return r;
}

__global__ void __launch_bounds__(NTHR, 2) k_fused(
        const float* __restrict__ means3d,
        const float* __restrict__ opacity,
        const float* __restrict__ scale3d,
        const float* __restrict__ features,
        const float* __restrict__ V,
        const float* __restrict__ P,
        float* __restrict__ out) {

    // 32KB region: input staging during projection, then sA/sB after rank
    __shared__ float4 sAB[2048];
    __shared__ unsigned long long uKey[1024];    // keys (8KB) / combine xb (5KB)
    __shared__ float M[16];
    __shared__ int s_cnt;

    float* stage = (float*)sAB;                  // [0,3072) means, [3072,4096) scale,
                                                 // [4096,5120) opacity, [5120,8192) features
    float4* sA = sAB;                            // [0,1024)  after staging dies
    float4* sB = sAB + 1024;                     // [1024,2048)
    unsigned long long* sKey = uKey;
    float* xb = (float*)uKey;

    const int tid  = threadIdx.x;
    const int lane = tid & 31;

    // ---- coalesced input staging (streaming, high MLP) ----
    #pragma unroll
    for (int i = 0; i < 6; i++) stage[tid + i * NTHR] = means3d[tid + i * NTHR];
    stage[3072 + tid] = scale3d[tid];
    stage[3072 + NTHR + tid] = scale3d[NTHR + tid];
    stage[4096 + tid] = opacity[tid];
    stage[4096 + NTHR + tid] = opacity[NTHR + tid];
    #pragma unroll
    for (int i = 0; i < 6; i++) stage[5120 + tid + i * NTHR] = features[tid + i * NTHR];

    // fused projection coefficients (ph0, ph1, ph3, tz) per (x,y,z,1)
    if (tid < 16) {
        int r = tid & 3, c = tid >> 2;
        float mm;
        if (c < 3) {
            int pc = (c == 2) ? 3 : c;
            mm = V[r*4+0]*P[0*4+pc] + V[r*4+1]*P[1*4+pc]
               + V[r*4+2]*P[2*4+pc] + V[r*4+3]*P[3*4+pc];
        } else {
            mm = V[r*4+2];
        }
        M[c*4 + r] = mm;
    }
    if (tid == 0) s_cnt = 0;

    const int bx = blockIdx.x & 15;
    const int by = blockIdx.x >> 4;
    const int x0 = bx * BLK_W;
    const int y0 = by * BLK_H;

    const float tu0 = (float)((x0 / TILE_SZ) * TILE_SZ);
    const float tv0 = (float)((y0 / TILE_SZ) * TILE_SZ);
    const float tu1 = tu0 + (float)TILE_SZ - 1.0f;
    const float tv1 = tv0 + (float)TILE_SZ - 1.0f;
    const float cx = (float)x0 + (BLK_W - 1) * 0.5f;
    const float cy = (float)y0 + (BLK_H - 1) * 0.5f;
    const float hw = (BLK_W - 1) * 0.5f + PAD;
    const float hh = (BLK_H - 1) * 0.5f + PAD;

    __syncthreads();                              // staging + M ready

    // ---- project 2 gaussians/thread from smem (bank-conflict-free) ----
    float4 A0, B0, A1, B1;
    unsigned long long k0 = 0, k1 = 0;
    bool m0 = false, m1 = false;
    int pc0 = 0;                                  // winners in it0 ballot (for base offset)
    int wbase = 0;
    unsigned bal0s = 0, bal1s = 0;
    int pre0 = 0, pre1 = 0;

    #pragma unroll
    for (int it = 0; it < 2; it++) {
        const int g = tid + it * NTHR;
        float x  = stage[3*g+0];
        float y  = stage[3*g+1];
        float z  = stage[3*g+2];
        float sc = stage[3072 + g];

        float ph0 = fmaf(x, M[0],  fmaf(y, M[1],  fmaf(z, M[2],  M[3])));
        float ph1 = fmaf(x, M[4],  fmaf(y, M[5],  fmaf(z, M[6],  M[7])));
        float ph3 = fmaf(x, M[8],  fmaf(y, M[9],  fmaf(z, M[10], M[11])));
        float tz  = fmaf(x, M[12], fmaf(y, M[13], fmaf(z, M[14], M[15])));

        float invw = frcp(ph3 + 1e-6f);
        float mx = fmaf(ph0 * invw, 128.0f, 127.5f);
        float my = fmaf(ph1 * invw, 128.0f, 127.5f);

        float rtz   = frcp(tz);
        float s2    = sc * FOCALF * rtz;
        float radii = 5.0f * s2;
        float rs2   = frcp(s2);
        float k2    = (-0.5f * LOG2E) * rs2 * rs2;

        // exact reference tile mask (unclamped rect equivalent for strict >)
        bool mTile = (fminf(mx + radii, tu1) > fmaxf(mx - radii, tu0)) &&
                     (fminf(my + radii, tv1) > fmaxf(my - radii, tv0));
        // circle-distance cull: dropped gaussians >= 5sigma+PAD from all px
        float ddx = fmaxf(fabsf(mx - cx) - hw, 0.0f);
        float ddy = fmaxf(fabsf(my - cy) - hh, 0.0f);
        bool mm = mTile && (fmaf(ddx, ddx, ddy * ddy) < radii * radii);

        unsigned bal = __ballot_sync(0xffffffffu, mm);
        if (mm) {
            unsigned ku = __float_as_uint(tz);
            ku = (ku & 0x80000000u) ? ~ku : (ku | 0x80000000u);
            unsigned long long kk = ((unsigned long long)ku << 32) | (unsigned)g;
            float lop = flg2(stage[4096 + g]);
            float fr = stage[5120 + 3*g+0];
            float fg = stage[5120 + 3*g+1];
            float fb = stage[5120 + 3*g+2];
            if (it == 0) { k0 = kk; A0 = make_float4(mx, my, k2, lop);
                           B0 = make_float4(fr, fg, fb, tz); }
            else         { k1 = kk; A1 = make_float4(mx, my, k2, lop);
                           B1 = make_float4(fr, fg, fb, tz); }
        }
        if (it == 0) { m0 = mm; bal0s = bal; pre0 = __popc(bal & ((1u << lane) - 1u)); pc0 = __popc(bal); }
        else         { m1 = mm; bal1s = bal; pre1 = __popc(bal & ((1u << lane) - 1u)); }
    }

    // single warp-aggregated atomic for both ballots
    {
        int total = pc0 + __popc(bal1s);
        if (lane == 0 && total) wbase = atomicAdd(&s_cnt, total);
        wbase = __shfl_sync(0xffffffffu, wbase, 0);
    }
    if (m0) sKey[wbase + pre0] = k0;
    if (m1) sKey[wbase + pc0 + pre1] = k1;
    __syncthreads();                              // keys ready; staging dead
    const int cnt = s_cnt;

    // ---- cooperative warp rank (lanes share key scans per winner) ----
    int r0 = -1, r1 = -1;
    for (unsigned b = bal0s; b; b &= b - 1) {
        int wl = __ffs(b) - 1;
        unsigned long long k = __shfl_sync(0xffffffffu, k0, wl);
        int c = 0;
        for (int j = lane; j < cnt; j += 32) c += (sKey[j] < k) ? 1 : 0;
        c = __reduce_add_sync(0xffffffffu, c);
        if (lane == wl) r0 = c;
    }
    for (unsigned b = bal1s; b; b &= b - 1) {
        int wl = __ffs(b) - 1;
        unsigned long long k = __shfl_sync(0xffffffffu, k1, wl);
        int c = 0;
        for (int j = lane; j < cnt; j += 32) c += (sKey[j] < k) ? 1 : 0;
        c = __reduce_add_sync(0xffffffffu, c);
        if (lane == wl) r1 = c;
    }
    if (m0) { sA[r0] = A0; sB[r0] = B0; }          // overlays dead staging
    if (m1) { sA[r1] = A1; sB[r1] = B1; }
    __syncthreads();                              // sorted lists ready

    // ---- split-list composite: 2 threads per pixel ----
    const int pxi = tid & (NPX - 1);
    const int px  = x0 + (pxi & (BLK_W - 1));
    const int py  = y0 + (pxi / BLK_W);
    const float fx = (float)px, fy = (float)py;
    const bool back = (tid >= NPX);

    const int half = (cnt + 1) >> 1;
    const int j0 = back ? half : 0;
    const int j1 = back ? cnt : half;

    float T = 1.0f;
    unsigned long long crg = 0ull, cbd = 0ull;

    #pragma unroll 4
    for (int j = j0; j < j1; j++) {
        float4 A = sA[j];
        float dx = fx - A.x;
        float dy = fy - A.y;
        float d2 = fmaf(dx, dx, dy * dy);
        float a  = fex2(fmaf(A.z, d2, A.w));      // = op*gw <= 0.95 < 0.99
        float w  = a * T;
        ulonglong2 B = reinterpret_cast<const ulonglong2*>(sB)[j];
        unsigned long long ww;
        unsigned wu = __float_as_uint(w);
        asm("mov.b64 %0, {%1, %1};" : "=l"(ww) : "r"(wu));
        asm("fma.rn.f32x2 %0, %1, %2, %3;" : "=l"(crg) : "l"(B.x), "l"(ww), "l"(crg));
        asm("fma.rn.f32x2 %0, %1, %2, %3;" : "=l"(cbd) : "l"(B.y), "l"(ww), "l"(cbd));
        T = fmaf(-a, T, T);
    }

    float cr, cg, cb, dsum;
    { unsigned lo, hi;
      asm("mov.b64 {%0, %1}, %2;" : "=r"(lo), "=r"(hi) : "l"(crg));
      cr = __uint_as_float(lo); cg = __uint_as_float(hi);
      asm("mov.b64 {%0, %1}, %2;" : "=r"(lo), "=r"(hi) : "l"(cbd));
      cb = __uint_as_float(lo); dsum = __uint_as_float(hi); }

    __syncthreads();                              // keys dead -> reuse as xb
    if (back) {
        xb[0*NPX + pxi] = cr;
        xb[1*NPX + pxi] = cg;
        xb[2*NPX + pxi] = cb;
        xb[3*NPX + pxi] = dsum;
        xb[4*NPX + pxi] = T;
    }
    __syncthreads();                              // xb ready

    if (!back) {
        // (C,T) o (C',T') = (C + T*C', T*T')  -- exact composition
        cr   = fmaf(T, xb[0*NPX + pxi], cr);
        cg   = fmaf(T, xb[1*NPX + pxi], cg);
        cb   = fmaf(T, xb[2*NPX + pxi], cb);
        dsum = fmaf(T, xb[3*NPX + pxi], dsum);
        T    = T * xb[4*NPX + pxi];

        float acc = 1.0f - T;
        float bg  = T;
        int pix = py * IMG_W + px;
        out[pix*3 + 0] = fminf(fmaxf(cr + bg, 0.0f), 1.0f);
        out[pix*3 + 1] = fminf(fmaxf(cg + bg, 0.0f), 1.0f);
        out[pix*3 + 2] = fminf(fmaxf(cb + bg, 0.0f), 1.0f);
        out[IMG_W*IMG_H*3 + pix] = dsum;
        out[IMG_W*IMG_H*4 + pix] = acc;
    }
}

extern "C" void kernel_launch(void* const* d_in, const int* in_sizes, int n_in,
                              void* d_out, int out_size) {
    const float* means3d  = (const float*)d_in[0];
    const float* opacity  = (const float*)d_in[1];
    const float* scale3d  = (const float*)d_in[2];
    const float* features = (const float*)d_in[3];
    const float* viewm    = (const float*)d_in[4];
    const float* projm    = (const float*)d_in[5];
    float* out = (float*)d_out;

    k_fused<<<NBLK, NTHR>>>(means3d, opacity, scale3d, features, viewm, projm, out);
}

// round 14
// speedup vs baseline: 1.2239x; 1.0239x over previous
#include <cuda_runtime.h>

#define NG      1024
#define IMG_W   256
#define IMG_H   256
#define TILE_SZ 64
#define FOCALF  256.0f
#define LOG2E   1.4426950408889634f

#define BLK_W   16
#define BLK_H   16
#define PAD     1.0f
#define CULLF   0.9f    // circle cull at 4.5 sigma (tile mask stays exact 5 sigma)
#define NBLK    ((IMG_W / BLK_W) * (IMG_H / BLK_H))   // 256
#define NTHR    512
#define NPX     (BLK_W * BLK_H)                        // 256

__device__ __forceinline__ float frcp(float x) {
    float r; asm("rcp.approx.ftz.f32 %0, %1;" : "=f"(r) : "f"(x)); return r;
}
__device__ __forceinline__ float flg2(float x) {
    float r; asm("lg2.approx.f32 %0, %1;" : "=f"(r) : "f"(x)); return r;
}
__device__ __forceinline__ float fex2(float x) {
    float r; asm("ex2.approx.ftz.f32 %0, %1;" : "=f"(r) : "f"(x)); return r;
}

__global__ void __launch_bounds__(NTHR, 2) k_fused(
        const float* __restrict__ means3d,
        const float* __restrict__ opacity,
        const float* __restrict__ scale3d,
        const float* __restrict__ features,
        const float* __restrict__ V,
        const float* __restrict__ P,
        float* __restrict__ out) {

    __shared__ float4 sA[NG];                    // (mx, my, k2, lg2(op))
    __shared__ float4 sB[NG];                    // (r, g, b, depth)
    __shared__ unsigned long long uKey[1024];    // keys (8KB) / combine xb (5KB)
    __shared__ float M[16];
    __shared__ int s_cnt;

    unsigned long long* sKey = uKey;
    float* xb = (float*)uKey;

    const int tid  = threadIdx.x;
    const int lane = tid & 31;

    // fused projection coefficients (ph0, ph1, ph3, tz) per (x,y,z,1)
    if (tid < 16) {
        int r = tid & 3, c = tid >> 2;
        float mm;
        if (c < 3) {
            int pc = (c == 2) ? 3 : c;
            mm = V[r*4+0]*P[0*4+pc] + V[r*4+1]*P[1*4+pc]
               + V[r*4+2]*P[2*4+pc] + V[r*4+3]*P[3*4+pc];
        } else {
            mm = V[r*4+2];
        }
        M[c*4 + r] = mm;
    }
    if (tid == 0) s_cnt = 0;

    const int bx = blockIdx.x & 15;
    const int by = blockIdx.x >> 4;
    const int x0 = bx * BLK_W;
    const int y0 = by * BLK_H;

    const float tu0 = (float)((x0 / TILE_SZ) * TILE_SZ);
    const float tv0 = (float)((y0 / TILE_SZ) * TILE_SZ);
    const float tu1 = tu0 + (float)TILE_SZ - 1.0f;
    const float tv1 = tv0 + (float)TILE_SZ - 1.0f;
    const float cx = (float)x0 + (BLK_W - 1) * 0.5f;
    const float cy = (float)y0 + (BLK_H - 1) * 0.5f;
    const float hw = (BLK_W - 1) * 0.5f + PAD;
    const float hh = (BLK_H - 1) * 0.5f + PAD;

    // prefetch both gaussians owned by this thread (overlaps M LDG chain)
    const int g0 = tid, g1 = tid + NTHR;
    float x_0 = means3d[3*g0+0], y_0 = means3d[3*g0+1], z_0 = means3d[3*g0+2];
    float x_1 = means3d[3*g1+0], y_1 = means3d[3*g1+1], z_1 = means3d[3*g1+2];
    float sc0 = scale3d[g0],  sc1 = scale3d[g1];
    float op0 = opacity[g0],  op1 = opacity[g1];
    float fr0 = features[3*g0+0], fg0 = features[3*g0+1], fb0 = features[3*g0+2];
    float fr1 = features[3*g1+0], fg1 = features[3*g1+1], fb1 = features[3*g1+2];

    __syncthreads();                              // M ready

    float4 A0, B0, A1, B1;
    unsigned long long k0 = 0, k1 = 0;
    bool m0, m1;

    #pragma unroll
    for (int it = 0; it < 2; it++) {
        float x = it ? x_1 : x_0, y = it ? y_1 : y_0, z = it ? z_1 : z_0;
        float sc = it ? sc1 : sc0, op = it ? op1 : op0;

        float ph0 = fmaf(x, M[0],  fmaf(y, M[1],  fmaf(z, M[2],  M[3])));
        float ph1 = fmaf(x, M[4],  fmaf(y, M[5],  fmaf(z, M[6],  M[7])));
        float ph3 = fmaf(x, M[8],  fmaf(y, M[9],  fmaf(z, M[10], M[11])));
        float tz  = fmaf(x, M[12], fmaf(y, M[13], fmaf(z, M[14], M[15])));

        float invw = frcp(ph3 + 1e-6f);
        float mx = fmaf(ph0 * invw, 128.0f, 127.5f);
        float my = fmaf(ph1 * invw, 128.0f, 127.5f);

        float rtz   = frcp(tz);
        float s2    = sc * FOCALF * rtz;
        float radii = 5.0f * s2;
        float rs2   = frcp(s2);
        float k2    = (-0.5f * LOG2E) * rs2 * rs2;

        // exact reference tile mask (5 sigma, unclamped equivalent for strict >)
        bool mTile = (fminf(mx + radii, tu1) > fmaxf(mx - radii, tu0)) &&
                     (fminf(my + radii, tv1) > fmaxf(my - radii, tv0));
        // circle-distance cull at 4.5 sigma + PAD: dropped weight <= 3.8e-5
        float rc  = CULLF * radii;
        float ddx = fmaxf(fabsf(mx - cx) - hw, 0.0f);
        float ddy = fmaxf(fabsf(my - cy) - hh, 0.0f);
        bool mm = mTile && (fmaf(ddx, ddx, ddy * ddy) < rc * rc);

        unsigned bal = __ballot_sync(0xffffffffu, mm);
        if (mm) {
            int prefix = __popc(bal & ((1u << lane) - 1u));
            int leader = __ffs(bal) - 1;
            int wbase = 0;
            if (lane == leader) wbase = atomicAdd(&s_cnt, __popc(bal));
            wbase = __shfl_sync(bal, wbase, leader);
            unsigned ku = __float_as_uint(tz);
            ku = (ku & 0x80000000u) ? ~ku : (ku | 0x80000000u);
            unsigned long long kk =
                ((unsigned long long)ku << 32) | (unsigned)(it ? g1 : g0);
            sKey[wbase + prefix] = kk;
            float lop = flg2(op);
            if (it == 0) { k0 = kk; A0 = make_float4(mx, my, k2, lop);
                           B0 = make_float4(fr0, fg0, fb0, tz); }
            else         { k1 = kk; A1 = make_float4(mx, my, k2, lop);
                           B1 = make_float4(fr1, fg1, fb1, tz); }
        }
        if (it == 0) m0 = mm; else m1 = mm;
    }
    unsigned bal0 = __ballot_sync(0xffffffffu, m0);
    unsigned bal1 = __ballot_sync(0xffffffffu, m1);

    __syncthreads();                              // keys ready
    const int cnt = s_cnt;

    // ---- cooperative warp rank (lanes share key scans per winner) ----
    int r0 = -1, r1 = -1;
    for (unsigned b = bal0; b; b &= b - 1) {
        int wl = __ffs(b) - 1;
        unsigned long long k = __shfl_sync(0xffffffffu, k0, wl);
        int c = 0;
        for (int j = lane; j < cnt; j += 32) c += (sKey[j] < k) ? 1 : 0;
        c = __reduce_add_sync(0xffffffffu, c);
        if (lane == wl) r0 = c;
    }
    for (unsigned b = bal1; b; b &= b - 1) {
        int wl = __ffs(b) - 1;
        unsigned long long k = __shfl_sync(0xffffffffu, k1, wl);
        int c = 0;
        for (int j = lane; j < cnt; j += 32) c += (sKey[j] < k) ? 1 : 0;
        c = __reduce_add_sync(0xffffffffu, c);
        if (lane == wl) r1 = c;
    }
    if (m0) { sA[r0] = A0; sB[r0] = B0; }
    if (m1) { sA[r1] = A1; sB[r1] = B1; }
    __syncthreads();                              // sorted lists ready; keys dead

    // ---- split-list composite: 2 threads per pixel ----
    const int pxi = tid & (NPX - 1);
    const int px  = x0 + (pxi & (BLK_W - 1));
    const int py  = y0 + (pxi / BLK_W);
    const float fx = (float)px, fy = (float)py;
    const bool back = (tid >= NPX);

    const int half = (cnt + 1) >> 1;
    const int j0 = back ? half : 0;
    const int j1 = back ? cnt : half;

    float T = 1.0f;
    unsigned long long crg = 0ull, cbd = 0ull;

    #pragma unroll 4
    for (int j = j0; j < j1; j++) {
        float4 A = sA[j];
        float dx = fx - A.x;
        float dy = fy - A.y;
        float d2 = fmaf(dx, dx, dy * dy);
        float a  = fex2(fmaf(A.z, d2, A.w));      // = op*gw <= 0.95 < 0.99
        float w  = a * T;
        ulonglong2 B = reinterpret_cast<const ulonglong2*>(sB)[j];
        unsigned long long ww;
        unsigned wu = __float_as_uint(w);
        asm("mov.b64 %0, {%1, %1};" : "=l"(ww) : "r"(wu));
        asm("fma.rn.f32x2 %0, %1, %2, %3;" : "=l"(crg) : "l"(B.x), "l"(ww), "l"(crg));
        asm("fma.rn.f32x2 %0, %1, %2, %3;" : "=l"(cbd) : "l"(B.y), "l"(ww), "l"(cbd));
        T = fmaf(-a, T, T);
    }

    float cr, cg, cb, dsum;
    { unsigned lo, hi;
      asm("mov.b64 {%0, %1}, %2;" : "=r"(lo), "=r"(hi) : "l"(crg));
      cr = __uint_as_float(lo); cg = __uint_as_float(hi);
      asm("mov.b64 {%0, %1}, %2;" : "=r"(lo), "=r"(hi) : "l"(cbd));
      cb = __uint_as_float(lo); dsum = __uint_as_float(hi); }

    // keys' last read was the rank phase (fenced above) -> xb write race-free
    if (back) {
        xb[0*NPX + pxi] = cr;
        xb[1*NPX + pxi] = cg;
        xb[2*NPX + pxi] = cb;
        xb[3*NPX + pxi] = dsum;
        xb[4*NPX + pxi] = T;
    }
    __syncthreads();                              // xb ready

    if (!back) {
        // (C,T) o (C',T') = (C + T*C', T*T')  -- exact composition
        cr   = fmaf(T, xb[0*NPX + pxi], cr);
        cg   = fmaf(T, xb[1*NPX + pxi], cg);
        cb   = fmaf(T, xb[2*NPX + pxi], cb);
        dsum = fmaf(T, xb[3*NPX + pxi], dsum);
        T    = T * xb[4*NPX + pxi];

        float acc = 1.0f - T;
        float bg  = T;
        int pix = py * IMG_W + px;
        out[pix*3 + 0] = fminf(fmaxf(cr + bg, 0.0f), 1.0f);
        out[pix*3 + 1] = fminf(fmaxf(cg + bg, 0.0f), 1.0f);
        out[pix*3 + 2] = fminf(fmaxf(cb + bg, 0.0f), 1.0f);
        out[IMG_W*IMG_H*3 + pix] = dsum;
        out[IMG_W*IMG_H*4 + pix] = acc;
    }
}

extern "C" void kernel_launch(void* const* d_in, const int* in_sizes, int n_in,
                              void* d_out, int out_size) {
    const float* means3d  = (const float*)d_in[0];
    const float* opacity  = (const float*)d_in[1];
    const float* scale3d  = (const float*)d_in[2];
    const float* features = (const float*)d_in[3];
    const float* viewm    = (const float*)d_in[4];
    const float* projm    = (const float*)d_in[5];
    float* out = (float*)d_out;

    k_fused<<<NBLK, NTHR>>>(means3d, opacity, scale3d, features, viewm, projm, out);
}

// round 15
// speedup vs baseline: 1.5074x; 1.2316x over previous
#include <cuda_runtime.h>

#define NG      1024
#define IMG_W   256
#define IMG_H   256
#define TILE_SZ 64
#define FOCALF  256.0f
#define LOG2E   1.4426950408889634f

#define BLK_W   16
#define BLK_H   16
#define PAD     1.0f
#define CULLF   0.8f    // circle cull at 4.0 sigma (tile mask stays exact 5 sigma)
#define NBLK    ((IMG_W / BLK_W) * (IMG_H / BLK_H))   // 256
#define NTHR    512
#define NPX     (BLK_W * BLK_H)                        // 256

__device__ __forceinline__ float frcp(float x) {
    float r; asm("rcp.approx.ftz.f32 %0, %1;" : "=f"(r) : "f"(x)); return r;
}
__device__ __forceinline__ float flg2(float x) {
    float r; asm("lg2.approx.f32 %0, %1;" : "=f"(r) : "f"(x)); return r;
}
__device__ __forceinline__ float fex2(float x) {
    float r; asm("ex2.approx.ftz.f32 %0, %1;" : "=f"(r) : "f"(x)); return r;
}

__global__ void __launch_bounds__(NTHR, 2) k_fused(
        const float* __restrict__ means3d,
        const float* __restrict__ opacity,
        const float* __restrict__ scale3d,
        const float* __restrict__ features,
        const float* __restrict__ V,
        const float* __restrict__ P,
        float* __restrict__ out) {

    __shared__ float4 sA[NG];                    // (mx, my, k2, lg2(op))
    __shared__ float4 sB[NG];                    // (r, g, b, depth)
    __shared__ unsigned long long uKey[1024];    // keys (8KB) / combine xb (5KB)
    __shared__ float M[16];
    __shared__ int s_cnt;

    unsigned long long* sKey = uKey;
    float* xb = (float*)uKey;

    const int tid  = threadIdx.x;
    const int lane = tid & 31;

    // fused projection coefficients (ph0, ph1, ph3, tz) per (x,y,z,1)
    if (tid < 16) {
        int r = tid & 3, c = tid >> 2;
        float mm;
        if (c < 3) {
            int pc = (c == 2) ? 3 : c;
            mm = V[r*4+0]*P[0*4+pc] + V[r*4+1]*P[1*4+pc]
               + V[r*4+2]*P[2*4+pc] + V[r*4+3]*P[3*4+pc];
        } else {
            mm = V[r*4+2];
        }
        M[c*4 + r] = mm;
    }
    if (tid == 0) s_cnt = 0;

    const int bx = blockIdx.x & 15;
    const int by = blockIdx.x >> 4;
    const int x0 = bx * BLK_W;
    const int y0 = by * BLK_H;

    const float tu0 = (float)((x0 / TILE_SZ) * TILE_SZ);
    const float tv0 = (float)((y0 / TILE_SZ) * TILE_SZ);
    const float tu1 = tu0 + (float)TILE_SZ - 1.0f;
    const float tv1 = tv0 + (float)TILE_SZ - 1.0f;
    const float cx = (float)x0 + (BLK_W - 1) * 0.5f;
    const float cy = (float)y0 + (BLK_H - 1) * 0.5f;
    const float hw = (BLK_W - 1) * 0.5f + PAD;
    const float hh = (BLK_H - 1) * 0.5f + PAD;

    // prefetch both gaussians owned by this thread (overlaps M LDG chain)
    const int g0 = tid, g1 = tid + NTHR;
    float x_0 = means3d[3*g0+0], y_0 = means3d[3*g0+1], z_0 = means3d[3*g0+2];
    float x_1 = means3d[3*g1+0], y_1 = means3d[3*g1+1], z_1 = means3d[3*g1+2];
    float sc0 = scale3d[g0],  sc1 = scale3d[g1];
    float op0 = opacity[g0],  op1 = opacity[g1];
    float fr0 = features[3*g0+0], fg0 = features[3*g0+1], fb0 = features[3*g0+2];
    float fr1 = features[3*g1+0], fg1 = features[3*g1+1], fb1 = features[3*g1+2];

    __syncthreads();                              // M ready

    float4 A0, B0, A1, B1;
    unsigned long long k0 = 0, k1 = 0;
    bool m0, m1;
    unsigned bal0 = 0, bal1 = 0;

    #pragma unroll
    for (int it = 0; it < 2; it++) {
        float x = it ? x_1 : x_0, y = it ? y_1 : y_0, z = it ? z_1 : z_0;
        float sc = it ? sc1 : sc0, op = it ? op1 : op0;

        float ph0 = fmaf(x, M[0],  fmaf(y, M[1],  fmaf(z, M[2],  M[3])));
        float ph1 = fmaf(x, M[4],  fmaf(y, M[5],  fmaf(z, M[6],  M[7])));
        float ph3 = fmaf(x, M[8],  fmaf(y, M[9],  fmaf(z, M[10], M[11])));
        float tz  = fmaf(x, M[12], fmaf(y, M[13], fmaf(z, M[14], M[15])));

        float invw = frcp(ph3 + 1e-6f);
        float mx = fmaf(ph0 * invw, 128.0f, 127.5f);
        float my = fmaf(ph1 * invw, 128.0f, 127.5f);

        float rtz   = frcp(tz);
        float s2    = sc * FOCALF * rtz;
        float radii = 5.0f * s2;
        float rs2   = frcp(s2);
        float k2    = (-0.5f * LOG2E) * rs2 * rs2;

        // exact reference tile mask (5 sigma, unclamped equivalent for strict >)
        bool mTile = (fminf(mx + radii, tu1) > fmaxf(mx - radii, tu0)) &&
                     (fminf(my + radii, tv1) > fmaxf(my - radii, tv0));
        // circle-distance cull at 4 sigma + PAD: dropped weight <= 3.2e-4
        float rc  = CULLF * radii;
        float ddx = fmaxf(fabsf(mx - cx) - hw, 0.0f);
        float ddy = fmaxf(fabsf(my - cy) - hh, 0.0f);
        bool mm = mTile && (fmaf(ddx, ddx, ddy * ddy) < rc * rc);

        unsigned bal = __ballot_sync(0xffffffffu, mm);
        if (mm) {
            int prefix = __popc(bal & ((1u << lane) - 1u));
            int leader = __ffs(bal) - 1;
            int wbase = 0;
            if (lane == leader) wbase = atomicAdd(&s_cnt, __popc(bal));
            wbase = __shfl_sync(bal, wbase, leader);
            unsigned ku = __float_as_uint(tz);
            ku = (ku & 0x80000000u) ? ~ku : (ku | 0x80000000u);
            unsigned long long kk =
                ((unsigned long long)ku << 32) | (unsigned)(it ? g1 : g0);
            sKey[wbase + prefix] = kk;
            float lop = flg2(op);
            if (it == 0) { k0 = kk; A0 = make_float4(mx, my, k2, lop);
                           B0 = make_float4(fr0, fg0, fb0, tz); }
            else         { k1 = kk; A1 = make_float4(mx, my, k2, lop);
                           B1 = make_float4(fr1, fg1, fb1, tz); }
        }
        if (it == 0) { m0 = mm; bal0 = bal; }
        else         { m1 = mm; bal1 = bal; }
    }

    __syncthreads();                              // keys ready
    const int cnt = s_cnt;

    // ---- cooperative warp rank (lanes share key scans per winner) ----
    int r0 = -1, r1 = -1;
    for (unsigned b = bal0; b; b &= b - 1) {
        int wl = __ffs(b) - 1;
        unsigned long long k = __shfl_sync(0xffffffffu, k0, wl);
        int c = 0;
        for (int j = lane; j < cnt; j += 32) c += (sKey[j] < k) ? 1 : 0;
        c = __reduce_add_sync(0xffffffffu, c);
        if (lane == wl) r0 = c;
    }
    for (unsigned b = bal1; b; b &= b - 1) {
        int wl = __ffs(b) - 1;
        unsigned long long k = __shfl_sync(0xffffffffu, k1, wl);
        int c = 0;
        for (int j = lane; j < cnt; j += 32) c += (sKey[j] < k) ? 1 : 0;
        c = __reduce_add_sync(0xffffffffu, c);
        if (lane == wl) r1 = c;
    }
    if (m0) { sA[r0] = A0; sB[r0] = B0; }
    if (m1) { sA[r1] = A1; sB[r1] = B1; }
    __syncthreads();                              // sorted lists ready; keys dead

    // ---- split-list composite: 2 threads per pixel ----
    const int pxi = tid & (NPX - 1);
    const int px  = x0 + (pxi & (BLK_W - 1));
    const int py  = y0 + (pxi / BLK_W);
    const float fx = (float)px, fy = (float)py;
    const bool back = (tid >= NPX);

    const int half = (cnt + 1) >> 1;
    const int j0 = back ? half : 0;
    const int j1 = back ? cnt : half;

    float T = 1.0f;
    unsigned long long crg = 0ull, cbd = 0ull;

    #pragma unroll 4
    for (int j = j0; j < j1; j++) {
        float4 A = sA[j];
        float dx = fx - A.x;
        float dy = fy - A.y;
        float d2 = fmaf(dx, dx, dy * dy);
        float a  = fex2(fmaf(A.z, d2, A.w));      // = op*gw <= 0.95 < 0.99
        float w  = a * T;
        ulonglong2 B = reinterpret_cast<const ulonglong2*>(sB)[j];
        unsigned long long ww;
        unsigned wu = __float_as_uint(w);
        asm("mov.b64 %0, {%1, %1};" : "=l"(ww) : "r"(wu));
        asm("fma.rn.f32x2 %0, %1, %2, %3;" : "=l"(crg) : "l"(B.x), "l"(ww), "l"(crg));
        asm("fma.rn.f32x2 %0, %1, %2, %3;" : "=l"(cbd) : "l"(B.y), "l"(ww), "l"(cbd));
        T = fmaf(-a, T, T);
    }

    float cr, cg, cb, dsum;
    { unsigned lo, hi;
      asm("mov.b64 {%0, %1}, %2;" : "=r"(lo), "=r"(hi) : "l"(crg));
      cr = __uint_as_float(lo); cg = __uint_as_float(hi);
      asm("mov.b64 {%0, %1}, %2;" : "=r"(lo), "=r"(hi) : "l"(cbd));
      cb = __uint_as_float(lo); dsum = __uint_as_float(hi); }

    // keys' last read was the rank phase (fenced above) -> xb write race-free
    if (back) {
        xb[0*NPX + pxi] = cr;
        xb[1*NPX + pxi] = cg;
        xb[2*NPX + pxi] = cb;
        xb[3*NPX + pxi] = dsum;
        xb[4*NPX + pxi] = T;
    }
    __syncthreads();                              // xb ready

    if (!back) {
        // (C,T) o (C',T') = (C + T*C', T*T')  -- exact composition
        cr   = fmaf(T, xb[0*NPX + pxi], cr);
        cg   = fmaf(T, xb[1*NPX + pxi], cg);
        cb   = fmaf(T, xb[2*NPX + pxi], cb);
        dsum = fmaf(T, xb[3*NPX + pxi], dsum);
        T    = T * xb[4*NPX + pxi];

        float acc = 1.0f - T;
        float bg  = T;
        int pix = py * IMG_W + px;
        out[pix*3 + 0] = fminf(fmaxf(cr + bg, 0.0f), 1.0f);
        out[pix*3 + 1] = fminf(fmaxf(cg + bg, 0.0f), 1.0f);
        out[pix*3 + 2] = fminf(fmaxf(cb + bg, 0.0f), 1.0f);
        out[IMG_W*IMG_H*3 + pix] = dsum;
        out[IMG_W*IMG_H*4 + pix] = acc;
    }
}

extern "C" void kernel_launch(void* const* d_in, const int* in_sizes, int n_in,
                              void* d_out, int out_size) {
    const float* means3d  = (const float*)d_in[0];
    const float* opacity  = (const float*)d_in[1];
    const float* scale3d  = (const float*)d_in[2];
    const float* features = (const float*)d_in[3];
    const float* viewm    = (const float*)d_in[4];
    const float* projm    = (const float*)d_in[5];
    float* out = (float*)d_out;

    k_fused<<<NBLK, NTHR>>>(means3d, opacity, scale3d, features, viewm, projm, out);
}

// round 16
// speedup vs baseline: 1.5129x; 1.0037x over previous
#include <cuda_runtime.h>

#define NG      1024
#define IMG_W   256
#define IMG_H   256
#define TILE_SZ 64
#define FOCALF  256.0f
#define LOG2E   1.4426950408889634f

#define BLK_W   16
#define BLK_H   16
#define PAD     1.0f
#define CULLF   0.7f    // circle cull at 3.5 sigma (tile mask stays exact 5 sigma)
#define NBLK    ((IMG_W / BLK_W) * (IMG_H / BLK_H))   // 256
#define NTHR    512
#define NPX     (BLK_W * BLK_H)                        // 256

__device__ __forceinline__ float frcp(float x) {
    float r; asm("rcp.approx.ftz.f32 %0, %1;" : "=f"(r) : "f"(x)); return r;
}
__device__ __forceinline__ float flg2(float x) {
    float r; asm("lg2.approx.f32 %0, %1;" : "=f"(r) : "f"(x)); return r;
}
__device__ __forceinline__ float fex2(float x) {
    float r; asm("ex2.approx.ftz.f32 %0, %1;" : "=f"(r) : "f"(x)); return r;
}

__global__ void __launch_bounds__(NTHR, 2) k_fused(
        const float* __restrict__ means3d,
        const float* __restrict__ opacity,
        const float* __restrict__ scale3d,
        const float* __restrict__ features,
        const float* __restrict__ V,
        const float* __restrict__ P,
        float* __restrict__ out) {

    __shared__ float4 sA[NG];                    // (mx, my, k2, lg2(op))
    __shared__ float4 sB[NG];                    // (r, g, b, depth)
    __shared__ unsigned long long uKey[1024];    // keys (8KB) / combine xb (5KB)
    __shared__ float M[16];
    __shared__ int s_cnt;

    unsigned long long* sKey = uKey;
    float* xb = (float*)uKey;

    const int tid  = threadIdx.x;
    const int lane = tid & 31;

    // fused projection coefficients (ph0, ph1, ph3, tz) per (x,y,z,1)
    if (tid < 16) {
        int r = tid & 3, c = tid >> 2;
        float mm;
        if (c < 3) {
            int pc = (c == 2) ? 3 : c;
            mm = V[r*4+0]*P[0*4+pc] + V[r*4+1]*P[1*4+pc]
               + V[r*4+2]*P[2*4+pc] + V[r*4+3]*P[3*4+pc];
        } else {
            mm = V[r*4+2];
        }
        M[c*4 + r] = mm;
    }
    if (tid == 0) s_cnt = 0;

    const int bx = blockIdx.x & 15;
    const int by = blockIdx.x >> 4;
    const int x0 = bx * BLK_W;
    const int y0 = by * BLK_H;

    const float tu0 = (float)((x0 / TILE_SZ) * TILE_SZ);
    const float tv0 = (float)((y0 / TILE_SZ) * TILE_SZ);
    const float tu1 = tu0 + (float)TILE_SZ - 1.0f;
    const float tv1 = tv0 + (float)TILE_SZ - 1.0f;
    const float cx = (float)x0 + (BLK_W - 1) * 0.5f;
    const float cy = (float)y0 + (BLK_H - 1) * 0.5f;
    const float hw = (BLK_W - 1) * 0.5f + PAD;
    const float hh = (BLK_H - 1) * 0.5f + PAD;

    // prefetch both gaussians owned by this thread (overlaps M LDG chain)
    const int g0 = tid, g1 = tid + NTHR;
    float x_0 = means3d[3*g0+0], y_0 = means3d[3*g0+1], z_0 = means3d[3*g0+2];
    float x_1 = means3d[3*g1+0], y_1 = means3d[3*g1+1], z_1 = means3d[3*g1+2];
    float sc0 = scale3d[g0],  sc1 = scale3d[g1];
    float op0 = opacity[g0],  op1 = opacity[g1];
    float fr0 = features[3*g0+0], fg0 = features[3*g0+1], fb0 = features[3*g0+2];
    float fr1 = features[3*g1+0], fg1 = features[3*g1+1], fb1 = features[3*g1+2];

    __syncthreads();                              // M ready

    float4 A0, B0, A1, B1;
    unsigned long long k0 = 0, k1 = 0;
    bool m0, m1;
    unsigned bal0 = 0, bal1 = 0;

    #pragma unroll
    for (int it = 0; it < 2; it++) {
        float x = it ? x_1 : x_0, y = it ? y_1 : y_0, z = it ? z_1 : z_0;
        float sc = it ? sc1 : sc0, op = it ? op1 : op0;

        float ph0 = fmaf(x, M[0],  fmaf(y, M[1],  fmaf(z, M[2],  M[3])));
        float ph1 = fmaf(x, M[4],  fmaf(y, M[5],  fmaf(z, M[6],  M[7])));
        float ph3 = fmaf(x, M[8],  fmaf(y, M[9],  fmaf(z, M[10], M[11])));
        float tz  = fmaf(x, M[12], fmaf(y, M[13], fmaf(z, M[14], M[15])));

        float invw = frcp(ph3 + 1e-6f);
        float mx = fmaf(ph0 * invw, 128.0f, 127.5f);
        float my = fmaf(ph1 * invw, 128.0f, 127.5f);

        float rtz   = frcp(tz);
        float s2    = sc * FOCALF * rtz;
        float radii = 5.0f * s2;
        float rs2   = frcp(s2);
        float k2    = (-0.5f * LOG2E) * rs2 * rs2;

        // exact reference tile mask (5 sigma, unclamped equivalent for strict >)
        bool mTile = (fminf(mx + radii, tu1) > fmaxf(mx - radii, tu0)) &&
                     (fminf(my + radii, tv1) > fmaxf(my - radii, tv0));
        // circle-distance cull at 3.5 sigma + PAD: dropped weight <= 2.1e-3*gw_margin
        float rc  = CULLF * radii;
        float ddx = fmaxf(fabsf(mx - cx) - hw, 0.0f);
        float ddy = fmaxf(fabsf(my - cy) - hh, 0.0f);
        bool mm = mTile && (fmaf(ddx, ddx, ddy * ddy) < rc * rc);

        unsigned bal = __ballot_sync(0xffffffffu, mm);
        if (mm) {
            int prefix = __popc(bal & ((1u << lane) - 1u));
            int leader = __ffs(bal) - 1;
            int wbase = 0;
            if (lane == leader) wbase = atomicAdd(&s_cnt, __popc(bal));
            wbase = __shfl_sync(bal, wbase, leader);
            unsigned ku = __float_as_uint(tz);
            ku = (ku & 0x80000000u) ? ~ku : (ku | 0x80000000u);
            unsigned long long kk =
                ((unsigned long long)ku << 32) | (unsigned)(it ? g1 : g0);
            sKey[wbase + prefix] = kk;
            float lop = flg2(op);
            if (it == 0) { k0 = kk; A0 = make_float4(mx, my, k2, lop);
                           B0 = make_float4(fr0, fg0, fb0, tz); }
            else         { k1 = kk; A1 = make_float4(mx, my, k2, lop);
                           B1 = make_float4(fr1, fg1, fb1, tz); }
        }
        if (it == 0) { m0 = mm; bal0 = bal; }
        else         { m1 = mm; bal1 = bal; }
    }

    __syncthreads();                              // keys ready
    const int cnt = s_cnt;

    // ---- cooperative warp rank (lanes share key scans per winner) ----
    int r0 = -1, r1 = -1;
    for (unsigned b = bal0; b; b &= b - 1) {
        int wl = __ffs(b) - 1;
        unsigned long long k = __shfl_sync(0xffffffffu, k0, wl);
        int c = 0;
        for (int j = lane; j < cnt; j += 32) c += (sKey[j] < k) ? 1 : 0;
        c = __reduce_add_sync(0xffffffffu, c);
        if (lane == wl) r0 = c;
    }
    for (unsigned b = bal1; b; b &= b - 1) {
        int wl = __ffs(b) - 1;
        unsigned long long k = __shfl_sync(0xffffffffu, k1, wl);
        int c = 0;
        for (int j = lane; j < cnt; j += 32) c += (sKey[j] < k) ? 1 : 0;
        c = __reduce_add_sync(0xffffffffu, c);
        if (lane == wl) r1 = c;
    }
    if (m0) { sA[r0] = A0; sB[r0] = B0; }
    if (m1) { sA[r1] = A1; sB[r1] = B1; }
    __syncthreads();                              // sorted lists ready; keys dead

    // ---- split-list composite: 2 threads per pixel ----
    const int pxi = tid & (NPX - 1);
    const int px  = x0 + (pxi & (BLK_W - 1));
    const int py  = y0 + (pxi / BLK_W);
    const float fx = (float)px, fy = (float)py;
    const bool back = (tid >= NPX);

    const int half = (cnt + 1) >> 1;
    const int j0 = back ? half : 0;
    const int j1 = back ? cnt : half;

    float T = 1.0f;
    unsigned long long crg = 0ull, cbd = 0ull;

    #pragma unroll 4
    for (int j = j0; j < j1; j++) {
        float4 A = sA[j];
        float dx = fx - A.x;
        float dy = fy - A.y;
        float d2 = fmaf(dx, dx, dy * dy);
        float a  = fex2(fmaf(A.z, d2, A.w));      // = op*gw <= 0.95 < 0.99
        float w  = a * T;
        ulonglong2 B = reinterpret_cast<const ulonglong2*>(sB)[j];
        unsigned long long ww;
        unsigned wu = __float_as_uint(w);
        asm("mov.b64 %0, {%1, %1};" : "=l"(ww) : "r"(wu));
        asm("fma.rn.f32x2 %0, %1, %2, %3;" : "=l"(crg) : "l"(B.x), "l"(ww), "l"(crg));
        asm("fma.rn.f32x2 %0, %1, %2, %3;" : "=l"(cbd) : "l"(B.y), "l"(ww), "l"(cbd));
        T = fmaf(-a, T, T);
    }

    float cr, cg, cb, dsum;
    { unsigned lo, hi;
      asm("mov.b64 {%0, %1}, %2;" : "=r"(lo), "=r"(hi) : "l"(crg));
      cr = __uint_as_float(lo); cg = __uint_as_float(hi);
      asm("mov.b64 {%0, %1}, %2;" : "=r"(lo), "=r"(hi) : "l"(cbd));
      cb = __uint_as_float(lo); dsum = __uint_as_float(hi); }

    // keys' last read was the rank phase (fenced above) -> xb write race-free
    if (back) {
        xb[0*NPX + pxi] = cr;
        xb[1*NPX + pxi] = cg;
        xb[2*NPX + pxi] = cb;
        xb[3*NPX + pxi] = dsum;
        xb[4*NPX + pxi] = T;
    }
    __syncthreads();                              // xb ready

    if (!back) {
        // (C,T) o (C',T') = (C + T*C', T*T')  -- exact composition
        cr   = fmaf(T, xb[0*NPX + pxi], cr);
        cg   = fmaf(T, xb[1*NPX + pxi], cg);
        cb   = fmaf(T, xb[2*NPX + pxi], cb);
        dsum = fmaf(T, xb[3*NPX + pxi], dsum);
        T    = T * xb[4*NPX + pxi];

        float acc = 1.0f - T;
        float bg  = T;
        int pix = py * IMG_W + px;
        out[pix*3 + 0] = fminf(fmaxf(cr + bg, 0.0f), 1.0f);
        out[pix*3 + 1] = fminf(fmaxf(cg + bg, 0.0f), 1.0f);
        out[pix*3 + 2] = fminf(fmaxf(cb + bg, 0.0f), 1.0f);
        out[IMG_W*IMG_H*3 + pix] = dsum;
        out[IMG_W*IMG_H*4 + pix] = acc;
    }
}

extern "C" void kernel_launch(void* const* d_in, const int* in_sizes, int n_in,
                              void* d_out, int out_size) {
    const float* means3d  = (const float*)d_in[0];
    const float* opacity  = (const float*)d_in[1];
    const float* scale3d  = (const float*)d_in[2];
    const float* features = (const float*)d_in[3];
    const float* viewm    = (const float*)d_in[4];
    const float* projm    = (const float*)d_in[5];
    float* out = (float*)d_out;

    k_fused<<<NBLK, NTHR>>>(means3d, opacity, scale3d, features, viewm, projm, out);
}